// round 10
// baseline (speedup 1.0000x reference)
#include <cuda_runtime.h>
#include <math.h>
#include <stdint.h>

#define BATCH 4096
#define KPTS  64
#define NMAT  65
#define TILE  (NMAT * NMAT)   /* 4225 */
#define GAMMA_C 0.5f
#define R2_POS  0.36f   /* 0.6^2  */
#define R2_NEG  1.44f   /* 1.2^2  */
#define NEGBIG  (-3.0e9f)
#define FXS     1048576.0f      /* 2^20 fixed-point scale for psum REDUX   */
#define FXS2    262144.0f       /* 2^18 fixed-point scale for fmax-sum REDUX */

__device__ float        g_partial[BATCH];   // per-block partial sums
__device__ unsigned int g_done;             // completion counter (self-resetting)

__device__ __forceinline__ bool read_mask(const void* p, size_t idx, unsigned mode) {
    if (mode & 2u) return ((const float*)p)[idx] != 0.0f;
    if (mode & 1u) return ((const uint8_t*)p)[idx] != 0;
    return ((const int*)p)[idx] != 0;
}

__global__ __launch_bounds__(256, 6) void loss_kernel(
    const float* __restrict__ pos_pts,   // (B,K,3)
    const float* __restrict__ anc_pts,   // (B,K,3)
    const void*  __restrict__ pos_m,     // (B,K) bool-ish
    const void*  __restrict__ anc_m,     // (B,K)
    const float* __restrict__ ms,        // (B,N,N)
    const float* __restrict__ T,         // (4,4)
    float*       __restrict__ out)
{
    __shared__ float smraw[TILE + 4];    // flat, stride 65 (odd) -> conflict-free everywhere used
    __shared__ float px[KPTS], py_[KPTS], pz[KPTS], pn[KPTS];
    __shared__ float ax[KPTS], ay[KPTS], az[KPTS], an[KPTS];
    __shared__ unsigned char s_pm[KPTS], s_am[KPTS];
    __shared__ float row_base[KPTS];     // Phase A: row psum  ->  after bases: base_row
    __shared__ int   row_cnt[KPTS];
    __shared__ float colp[8][KPTS];      // per-warp partials: psum (A) -> fmax-sums (sweep)
    __shared__ int   colc[8][KPTS];
    __shared__ float base_col[KPTS];
    __shared__ int   ccnt[KPTS];
    __shared__ float  warp_sum[8];
    __shared__ double dsum[8];
    __shared__ int    s_last;

    const int b    = blockIdx.x;
    const int tid  = threadIdx.x;
    const int lane = tid & 31;
    const int w    = tid >> 5;

    // ---- tile copy via cp.async, 16B aligned both sides (TILE % 4 == 1) ----
    const float* msb  = ms + (size_t)b * TILE;
    const int    head = (4 - (b & 3)) & 3;
    float* sm = smraw + ((4 - head) & 3);
    {
        const int nvec = (TILE - head) >> 2;
        const float* gsrc = msb + head;
        unsigned sdst = (unsigned)__cvta_generic_to_shared(sm + head);
        #pragma unroll
        for (int it = 0; it < 5; ++it) {
            int i = tid + it * 256;
            if (i < nvec)
                asm volatile("cp.async.cg.shared.global [%0], [%1], 16;"
                             :: "r"(sdst + i * 16), "l"(gsrc + i * 4));
        }
        asm volatile("cp.async.commit_group;");
        if (tid < head) sm[tid] = msb[tid];                 // head scalars (<=3)
        const int tstart = head + (nvec << 2);
        const int tcnt   = TILE - tstart;                   // tail scalars (<=3)
        if (tid >= 4 && tid < 4 + tcnt) sm[tstart + (tid - 4)] = msb[tstart + (tid - 4)];
    }

    // ---- in-block mask dtype detection on a fixed 2KB window (L2-broadcast) ----
    unsigned f = 0;
    {
        const unsigned int* mw = (const unsigned int*)pos_m;
        #pragma unroll
        for (int it = 0; it < 2; ++it) {
            unsigned v = mw[tid + it * 256];
            if (v == 0x3F800000u) f |= 2u;
            else if (v > 1u)      f |= 1u;
        }
    }
    const unsigned mode = (unsigned)__syncthreads_or((int)f);

    // ---- points / transformed anchors / masks ----
    if (tid < 64) {
        const float* p = pos_pts + ((size_t)b * KPTS + tid) * 3;
        float x = p[0], y = p[1], z = p[2];
        px[tid] = x; py_[tid] = y; pz[tid] = z;
        pn[tid] = x * x + y * y + z * z;
    } else if (tid < 128) {
        int k = tid - 64;
        const float* p = anc_pts + ((size_t)b * KPTS + k) * 3;
        float x = p[0], y = p[1], z = p[2];
        float X = T[0] * x + T[1] * y + T[2]  * z + T[3];
        float Y = T[4] * x + T[5] * y + T[6]  * z + T[7];
        float Z = T[8] * x + T[9] * y + T[10] * z + T[11];
        ax[k] = X; ay[k] = Y; az[k] = Z;
        an[k] = X * X + Y * Y + Z * Z;
    } else if (tid < 192) {
        int k = tid - 128;
        s_pm[k] = read_mask(pos_m, (size_t)b * KPTS + k, mode) ? 1 : 0;
    } else {
        int k = tid - 192;
        s_am[k] = read_mask(anc_m, (size_t)b * KPTS + k, mode) ? 1 : 0;
    }
    asm volatile("cp.async.wait_group 0;");
    __syncthreads();

    // ========== Phase A: geometry + pos-psums + neg-mask folded into data =====
    // Warp w owns rows [8w, 8w+8). Lane owns cols j0=lane, j1=lane+32.
    {
        const int j0 = lane, j1 = lane + 32;
        const float ax0 = ax[j0], ay0 = ay[j0], az0 = az[j0], an0 = an[j0];
        const float ax1 = ax[j1], ay1 = ay[j1], az1 = az[j1], an1 = an[j1];
        const bool  am0 = s_am[j0], am1 = s_am[j1];
        float cpsA = 0.0f, cpsB = 0.0f;
        int   ccA = 0, ccB = 0;
        #pragma unroll
        for (int r = 0; r < 8; ++r) {
            const int   i   = w * 8 + r;
            const float Xi = px[i], Yi = py_[i], Zi = pz[i], Ni = pn[i];
            const bool  pmk = s_pm[i];
            // mimic reference: (x2 - 2xy) + y2
            float d0 = (Ni - 2.0f * (Xi * ax0 + Yi * ay0 + Zi * az0)) + an0;
            float d1 = (Ni - 2.0f * (Xi * ax1 + Yi * ay1 + Zi * az1)) + an1;
            float m0 = sm[i * NMAT + j0];
            float m1 = sm[i * NMAT + j1];
            const bool c0 = (d0 < R2_POS) && pmk && am0;
            const bool c1 = (d1 < R2_POS) && pmk && am1;
            const float p0 = c0 ? -m0 : 0.0f;
            const float p1 = c1 ? -m1 : 0.0f;
            // row psum via fixed-point hardware reduction (abs error < 2e-5)
            int rps = __reduce_add_sync(0xFFFFFFFFu, __float2int_rn((p0 + p1) * FXS));
            int rc  = __reduce_add_sync(0xFFFFFFFFu, (int)c0 + (int)c1);
            if (lane == 0) {
                row_base[i] = (float)rps * (1.0f / FXS);   // raw psum for now
                row_cnt[i]  = rc;
            }
            cpsA += p0; cpsB += p1; ccA += (int)c0; ccB += (int)c1;
            // fold neg mask into the data: non-neg interior -> -3e9 (fmax kills it)
            if (!(d0 > R2_NEG)) sm[i * NMAT + j0] = NEGBIG;
            if (!(d1 > R2_NEG)) sm[i * NMAT + j1] = NEGBIG;
        }
        colp[w][j0] = cpsA; colp[w][j1] = cpsB;
        colc[w][j0] = ccA;  colc[w][j1] = ccB;
    }
    __syncthreads();

    // ========== bases: base_row (threads 0..63), base_col (threads 64..127) ====
    if (tid < 64) {
        float ps = row_base[tid]; int c = row_cnt[tid];
        float sl = sm[tid * NMAT + KPTS];
        row_base[tid] = (c ? __fdividef(ps, (float)c) : -sl) + GAMMA_C;
    } else if (tid < 128) {
        const int j = tid - 64;
        float p = 0.0f; int c = 0;
        #pragma unroll
        for (int t = 0; t < 8; ++t) { p += colp[t][j]; c += colc[t][j]; }
        float sl = sm[KPTS * NMAT + j];
        base_col[j] = (c ? __fdividef(p, (float)c) : -sl) + GAMMA_C;
        ccnt[j] = c;
    }
    __syncthreads();

    // ========== fused sweep: each element read ONCE, feeds both losses ========
    float acc = 0.0f;
    {
        const int j0 = lane, j1 = lane + 32;
        const float bc0 = base_col[j0], bc1 = base_col[j1];
        float ca = 0.0f, cb = 0.0f;
        #pragma unroll
        for (int r = 0; r < 8; ++r) {
            const int   i  = w * 8 + r;
            const float br = row_base[i];
            const float m0 = sm[i * NMAT + j0];
            const float m1 = sm[i * NMAT + j1];
            const float f0 = fmaxf(br + m0, 0.0f);
            const float f1 = fmaxf(br + m1, 0.0f);
            int rs = __reduce_add_sync(0xFFFFFFFFu, __float2int_rn((f0 + f1) * FXS2));
            if (lane == r) {                       // distribute logs across lanes 0..7
                float st = (float)rs * (1.0f / FXS2);
                if (row_cnt[i]) st += fmaxf(br + sm[i * NMAT + KPTS], 0.0f);
                acc += __logf(st + 1.0f);
            }
            ca += fmaxf(bc0 + m0, 0.0f);
            cb += fmaxf(bc1 + m1, 0.0f);
        }
        colp[w][j0] = ca; colp[w][j1] = cb;        // buffer reused (psums consumed)
    }
    __syncthreads();

    // ---- column finalize (threads 0..63) ----
    if (tid < 64) {
        float s = 0.0f;
        #pragma unroll
        for (int t = 0; t < 8; ++t) s += colp[t][tid];
        if (ccnt[tid]) s += fmaxf(base_col[tid] + sm[KPTS * NMAT + tid], 0.0f);
        acc += __logf(s + 1.0f);
    }

    // ---- block reduce ----
    #pragma unroll
    for (int o = 16; o; o >>= 1) acc += __shfl_xor_sync(0xFFFFFFFFu, acc, o);
    if (lane == 0) warp_sum[w] = acc;
    __syncthreads();
    if (tid == 0) {
        float tot = 0.0f;
        #pragma unroll
        for (int i = 0; i < 8; ++i) tot += warp_sum[i];
        g_partial[b] = tot;
        __threadfence();
        unsigned prev = atomicAdd(&g_done, 1u);
        s_last = (prev == BATCH - 1) ? 1 : 0;
    }
    __syncthreads();

    // ---- last block finalizes (no extra launch) ----
    if (s_last) {
        __threadfence();
        double d = 0.0;
        for (int i = tid; i < BATCH; i += 256) d += (double)g_partial[i];
        #pragma unroll
        for (int o = 16; o; o >>= 1) d += __shfl_xor_sync(0xFFFFFFFFu, d, o);
        if (lane == 0) dsum[w] = d;
        __syncthreads();
        if (tid == 0) {
            double t = 0.0;
            #pragma unroll
            for (int i = 0; i < 8; ++i) t += dsum[i];
            out[0] = (float)(t * (1.0 / (2.0 * (double)BATCH * (double)KPTS)));
            g_done = 0u;   // self-reset -> graph-replay deterministic
        }
    }
}

extern "C" void kernel_launch(void* const* d_in, const int* in_sizes, int n_in,
                              void* d_out, int out_size) {
    const float* pos_pts = (const float*)d_in[0];
    const float* anc_pts = (const float*)d_in[1];
    const void*  pos_m   = d_in[2];
    const void*  anc_m   = d_in[3];
    const float* ms      = (const float*)d_in[4];
    const float* T       = (const float*)d_in[5];

    loss_kernel<<<BATCH, 256>>>(pos_pts, anc_pts, pos_m, anc_m, ms, T, (float*)d_out);
}

// round 11
// speedup vs baseline: 1.7149x; 1.7149x over previous
#include <cuda_runtime.h>
#include <math.h>
#include <stdint.h>

#define BATCH 4096
#define KPTS  64
#define NMAT  65
#define TILE  (NMAT * NMAT)   /* 4225 */
#define GAMMA_C 0.5f
#define R2_POS  0.36f   /* 0.6^2  */
#define R2_NEG  1.44f   /* 1.2^2  */
#define NEGBIG  (-3.0e9f)
#define FXS     1048576.0f      /* 2^20 fixed-point scale for psum REDUX */

__device__ float        g_partial[BATCH];   // per-block partial sums
__device__ unsigned int g_done;             // completion counter (self-resetting)

__device__ __forceinline__ bool read_mask(const void* p, size_t idx, unsigned mode) {
    if (mode & 2u) return ((const float*)p)[idx] != 0.0f;
    if (mode & 1u) return ((const uint8_t*)p)[idx] != 0;
    return ((const int*)p)[idx] != 0;
}

__global__ __launch_bounds__(256, 6) void loss_kernel(
    const float* __restrict__ pos_pts,   // (B,K,3)
    const float* __restrict__ anc_pts,   // (B,K,3)
    const void*  __restrict__ pos_m,     // (B,K) bool-ish
    const void*  __restrict__ anc_m,     // (B,K)
    const float* __restrict__ ms,        // (B,N,N)
    const float* __restrict__ T,         // (4,4)
    float*       __restrict__ out)
{
    __shared__ float smraw[TILE + 4];    // flat, stride 65 (odd) -> rows AND cols conflict-free
    __shared__ float px[KPTS], py_[KPTS], pz[KPTS], pn[KPTS];
    __shared__ float ax[KPTS], ay[KPTS], az[KPTS], an[KPTS];
    __shared__ unsigned char s_pm[KPTS], s_am[KPTS];
    __shared__ float row_ps[KPTS];
    __shared__ int   row_cnt[KPTS];
    __shared__ float colp[8][KPTS];      // per-warp column psum partials
    __shared__ int   colc[8][KPTS];
    __shared__ float comb_s[128][2];
    __shared__ float  warp_sum[8];
    __shared__ double dsum[8];
    __shared__ int    s_last;

    const int b    = blockIdx.x;
    const int tid  = threadIdx.x;
    const int lane = tid & 31;
    const int w    = tid >> 5;

    // ---- tile copy via cp.async: 16B aligned both sides (TILE % 4 == 1) ----
    const float* msb  = ms + (size_t)b * TILE;
    const int    head = (4 - (b & 3)) & 3;
    float* sm = smraw + ((4 - head) & 3);
    {
        const int nvec = (TILE - head) >> 2;
        const float* gsrc = msb + head;
        unsigned sdst = (unsigned)__cvta_generic_to_shared(sm + head);
        #pragma unroll
        for (int it = 0; it < 5; ++it) {
            int i = tid + it * 256;
            if (i < nvec)
                asm volatile("cp.async.cg.shared.global [%0], [%1], 16;"
                             :: "r"(sdst + i * 16), "l"(gsrc + i * 4));
        }
        asm volatile("cp.async.commit_group;");
        if (tid < head) sm[tid] = msb[tid];                 // head scalars (<=3)
        const int tstart = head + (nvec << 2);
        const int tcnt   = TILE - tstart;                   // tail scalars (<=3)
        if (tid >= 4 && tid < 4 + tcnt) sm[tstart + (tid - 4)] = msb[tstart + (tid - 4)];
    }

    // ---- per-warp mask dtype detection (no block barrier). All warps scan the
    // same 32 L1-broadcast words: u8 packed words are >1 (0x01010101...),
    // f32 true == 0x3F800000 exactly, i32 words are only 0/1.
    unsigned mode;
    {
        unsigned v = ((const unsigned int*)pos_m)[lane];
        unsigned f = (v == 0x3F800000u) ? 2u : ((v > 1u) ? 1u : 0u);
        mode = __reduce_or_sync(0xFFFFFFFFu, f);
    }

    // ---- points / transformed anchors / masks ----
    if (tid < 64) {
        const float* p = pos_pts + ((size_t)b * KPTS + tid) * 3;
        float x = p[0], y = p[1], z = p[2];
        px[tid] = x; py_[tid] = y; pz[tid] = z;
        pn[tid] = x * x + y * y + z * z;
    } else if (tid < 128) {
        int k = tid - 64;
        const float* p = anc_pts + ((size_t)b * KPTS + k) * 3;
        float x = p[0], y = p[1], z = p[2];
        float X = T[0] * x + T[1] * y + T[2]  * z + T[3];
        float Y = T[4] * x + T[5] * y + T[6]  * z + T[7];
        float Z = T[8] * x + T[9] * y + T[10] * z + T[11];
        ax[k] = X; ay[k] = Y; az[k] = Z;
        an[k] = X * X + Y * Y + Z * Z;
    } else if (tid < 192) {
        int k = tid - 128;
        s_pm[k] = read_mask(pos_m, (size_t)b * KPTS + k, mode) ? 1 : 0;
    } else {
        int k = tid - 192;
        s_am[k] = read_mask(anc_m, (size_t)b * KPTS + k, mode) ? 1 : 0;
    }
    asm volatile("cp.async.wait_group 0;");
    __syncthreads();

    // ========== Phase A: geometry + pos-psums + neg-mask folded into data =====
    // Warp w owns rows [8w, 8w+8). Lane owns cols j0=lane, j1=lane+32.
    {
        const int j0 = lane, j1 = lane + 32;
        const float ax0 = ax[j0], ay0 = ay[j0], az0 = az[j0], an0 = an[j0];
        const float ax1 = ax[j1], ay1 = ay[j1], az1 = az[j1], an1 = an[j1];
        const bool  am0 = s_am[j0], am1 = s_am[j1];
        float cpsA = 0.0f, cpsB = 0.0f;
        int   ccA = 0, ccB = 0;
        #pragma unroll
        for (int r = 0; r < 8; ++r) {
            const int   i   = w * 8 + r;
            const float Xi = px[i], Yi = py_[i], Zi = pz[i], Ni = pn[i];
            const bool  pmk = s_pm[i];
            // mimic reference: (x2 - 2xy) + y2
            float d0 = (Ni - 2.0f * (Xi * ax0 + Yi * ay0 + Zi * az0)) + an0;
            float d1 = (Ni - 2.0f * (Xi * ax1 + Yi * ay1 + Zi * az1)) + an1;
            float m0 = sm[i * NMAT + j0];
            float m1 = sm[i * NMAT + j1];
            const bool c0 = (d0 < R2_POS) && pmk && am0;
            const bool c1 = (d1 < R2_POS) && pmk && am1;
            const float p0 = c0 ? -m0 : 0.0f;
            const float p1 = c1 ? -m1 : 0.0f;
            // row psum via fixed-point hardware reduction (abs error < 2e-5)
            int rps = __reduce_add_sync(0xFFFFFFFFu, __float2int_rn((p0 + p1) * FXS));
            int rc  = __reduce_add_sync(0xFFFFFFFFu, (int)c0 + (int)c1);
            if (lane == 0) {
                row_ps[i]  = (float)rps * (1.0f / FXS);
                row_cnt[i] = rc;
            }
            cpsA += p0; cpsB += p1; ccA += (int)c0; ccB += (int)c1;
            // fold neg mask into the data: non-neg interior -> -3e9 (fmax kills it)
            if (!(d0 > R2_NEG)) sm[i * NMAT + j0] = NEGBIG;
            if (!(d1 > R2_NEG)) sm[i * NMAT + j1] = NEGBIG;
        }
        colp[w][j0] = cpsA; colp[w][j1] = cpsB;
        colc[w][j0] = ccA;  colc[w][j1] = ccB;
    }
    __syncthreads();

    // ========== Phase B: branch-free loss sweeps (rows: pass 0, cols: pass 1) ==
    const int pass = tid >> 7;
    const int rr   = tid & 127;
    const int idx  = rr & 63;
    const int h    = rr >> 6;
    const int g    = (pass << 6) | idx;

    float psum; int cnt; float slack_m;
    if (pass == 0) {
        psum = row_ps[idx]; cnt = row_cnt[idx];
        slack_m = sm[idx * NMAT + KPTS];
    } else {
        float p = 0.0f; int c = 0;
        #pragma unroll
        for (int t = 0; t < 8; ++t) { p += colp[t][idx]; c += colc[t][idx]; }
        psum = p; cnt = c;
        slack_m = sm[KPTS * NMAT + idx];
    }
    const float base = (cnt ? __fdividef(psum, (float)cnt) : -slack_m) + GAMMA_C;

    float sA = 0.0f, sB = 0.0f;
    if (pass == 0) {
        const float* row = &sm[idx * NMAT + h * 32];
        #pragma unroll
        for (int jj = 0; jj < 16; ++jj) {
            sA += fmaxf(base + row[jj],      0.0f);
            sB += fmaxf(base + row[jj + 16], 0.0f);
        }
    } else {
        const float* colptr = &sm[(h * 32) * NMAT + idx];
        #pragma unroll
        for (int kk = 0; kk < 16; ++kk) {
            sA += fmaxf(base + colptr[kk * NMAT],        0.0f);
            sB += fmaxf(base + colptr[(kk + 16) * NMAT], 0.0f);
        }
    }
    comb_s[g][h] = sA + sB;
    __syncthreads();

    float acc = 0.0f;
    if (h == 0) {
        float st = comb_s[g][0] + comb_s[g][1];
        if (cnt) st += fmaxf(base + slack_m, 0.0f);   // slack entry: !row_none / !col_none
        acc = __logf(st + 1.0f);
    }

    // ---- block reduce ----
    #pragma unroll
    for (int o = 16; o; o >>= 1) acc += __shfl_xor_sync(0xFFFFFFFFu, acc, o);
    if (lane == 0) warp_sum[w] = acc;
    __syncthreads();
    if (tid == 0) {
        float tot = 0.0f;
        #pragma unroll
        for (int i = 0; i < 8; ++i) tot += warp_sum[i];
        g_partial[b] = tot;
        __threadfence();
        unsigned prev = atomicAdd(&g_done, 1u);
        s_last = (prev == BATCH - 1) ? 1 : 0;
    }
    __syncthreads();

    // ---- last block finalizes (no extra launch) ----
    if (s_last) {
        __threadfence();
        double d = 0.0;
        for (int i = tid; i < BATCH; i += 256) d += (double)g_partial[i];
        #pragma unroll
        for (int o = 16; o; o >>= 1) d += __shfl_xor_sync(0xFFFFFFFFu, d, o);
        if (lane == 0) dsum[w] = d;
        __syncthreads();
        if (tid == 0) {
            double t = 0.0;
            #pragma unroll
            for (int i = 0; i < 8; ++i) t += dsum[i];
            out[0] = (float)(t * (1.0 / (2.0 * (double)BATCH * (double)KPTS)));
            g_done = 0u;   // self-reset -> graph-replay deterministic
        }
    }
}

extern "C" void kernel_launch(void* const* d_in, const int* in_sizes, int n_in,
                              void* d_out, int out_size) {
    const float* pos_pts = (const float*)d_in[0];
    const float* anc_pts = (const float*)d_in[1];
    const void*  pos_m   = d_in[2];
    const void*  anc_m   = d_in[3];
    const float* ms      = (const float*)d_in[4];
    const float* T       = (const float*)d_in[5];

    loss_kernel<<<BATCH, 256>>>(pos_pts, anc_pts, pos_m, anc_m, ms, T, (float*)d_out);
}

// round 12
// speedup vs baseline: 1.7357x; 1.0121x over previous
#include <cuda_runtime.h>
#include <math.h>
#include <stdint.h>

#define BATCH 4096
#define KPTS  64
#define NMAT  65
#define TILE  (NMAT * NMAT)   /* 4225 */
#define GAMMA_C 0.5f
#define R2_POS  0.36f   /* 0.6^2  */
#define R2_NEG  1.44f   /* 1.2^2  */
#define NEGBIG  (-3.0e9f)
#define FXS     1048576.0f      /* 2^20 fixed-point scale for psum REDUX */

__device__ float        g_partial[BATCH];   // per-block partial sums
__device__ unsigned int g_done;             // completion counter (self-resetting)

__device__ __forceinline__ bool read_mask(const void* p, size_t idx, unsigned mode) {
    if (mode & 2u) return ((const float*)p)[idx] != 0.0f;
    if (mode & 1u) return ((const uint8_t*)p)[idx] != 0;
    return ((const int*)p)[idx] != 0;
}

__global__ __launch_bounds__(256, 7) void loss_kernel(
    const float* __restrict__ pos_pts,   // (B,K,3)
    const float* __restrict__ anc_pts,   // (B,K,3)
    const void*  __restrict__ pos_m,     // (B,K) bool-ish
    const void*  __restrict__ anc_m,     // (B,K)
    const float* __restrict__ ms,        // (B,N,N)
    const float* __restrict__ T,         // (4,4)
    float*       __restrict__ out)
{
    __shared__ __align__(16) float smraw[TILE + 4];  // stride 65 (odd): rows AND cols conflict-free
    __shared__ __align__(8) unsigned long long mbar; // TMA completion barrier
    __shared__ float px[KPTS], py_[KPTS], pz[KPTS], pn[KPTS];
    __shared__ float ax[KPTS], ay[KPTS], az[KPTS], an[KPTS];
    __shared__ unsigned char s_pm[KPTS], s_am[KPTS];
    __shared__ float row_ps[KPTS];
    __shared__ int   row_cnt[KPTS];
    __shared__ float colp[8][KPTS];      // per-warp column psum partials
    __shared__ int   colc[8][KPTS];
    __shared__ float comb_s[128][2];
    __shared__ float  warp_sum[8];
    __shared__ double dsum[8];
    __shared__ int    s_last;

    const int b    = blockIdx.x;
    const int tid  = threadIdx.x;
    const int lane = tid & 31;
    const int w    = tid >> 5;

    // ---- tile copy via ONE bulk-TMA request (16B aligned both sides).
    // TILE % 4 == 1 -> head peel makes (msb+head) 16B aligned; shifting the
    // shared base makes (sm+head) also 16B aligned (offset is 0 or 4 floats).
    const float* msb  = ms + (size_t)b * TILE;
    const int    head = (4 - (b & 3)) & 3;
    float* sm = smraw + ((4 - head) & 3);
    const int nvec   = (TILE - head) >> 2;
    const int nbytes = nvec << 4;
    {
        unsigned mb   = (unsigned)__cvta_generic_to_shared(&mbar);
        unsigned sdst = (unsigned)__cvta_generic_to_shared(sm + head);
        if (tid == 0) {
            asm volatile("mbarrier.init.shared.b64 [%0], 1;" :: "r"(mb));
            asm volatile("mbarrier.arrive.expect_tx.shared.b64 _, [%0], %1;"
                         :: "r"(mb), "r"(nbytes));
            asm volatile("cp.async.bulk.shared::cta.global.mbarrier::complete_tx::bytes "
                         "[%0], [%1], %2, [%3];"
                         :: "r"(sdst), "l"(msb + head), "r"(nbytes), "r"(mb) : "memory");
        }
        if (tid < head) sm[tid] = msb[tid];                 // head scalars (<=3)
        const int tstart = head + (nvec << 2);
        const int tcnt   = TILE - tstart;                   // tail scalars (<=3)
        if (tid >= 4 && tid < 4 + tcnt) sm[tstart + (tid - 4)] = msb[tstart + (tid - 4)];
    }

    // ---- per-warp mask dtype detection (no block barrier). All warps scan the
    // same 32 L1-broadcast words: u8 packed words are >1 (0x01010101...),
    // f32 true == 0x3F800000 exactly, i32 words are only 0/1.
    unsigned mode;
    {
        unsigned v = ((const unsigned int*)pos_m)[lane];
        unsigned f = (v == 0x3F800000u) ? 2u : ((v > 1u) ? 1u : 0u);
        mode = __reduce_or_sync(0xFFFFFFFFu, f);
    }

    // ---- points / transformed anchors / masks ----
    if (tid < 64) {
        const float* p = pos_pts + ((size_t)b * KPTS + tid) * 3;
        float x = p[0], y = p[1], z = p[2];
        px[tid] = x; py_[tid] = y; pz[tid] = z;
        pn[tid] = x * x + y * y + z * z;
    } else if (tid < 128) {
        int k = tid - 64;
        const float* p = anc_pts + ((size_t)b * KPTS + k) * 3;
        float x = p[0], y = p[1], z = p[2];
        float X = T[0] * x + T[1] * y + T[2]  * z + T[3];
        float Y = T[4] * x + T[5] * y + T[6]  * z + T[7];
        float Z = T[8] * x + T[9] * y + T[10] * z + T[11];
        ax[k] = X; ay[k] = Y; az[k] = Z;
        an[k] = X * X + Y * Y + Z * Z;
    } else if (tid < 192) {
        int k = tid - 128;
        s_pm[k] = read_mask(pos_m, (size_t)b * KPTS + k, mode) ? 1 : 0;
    } else {
        int k = tid - 192;
        s_am[k] = read_mask(anc_m, (size_t)b * KPTS + k, mode) ? 1 : 0;
    }
    __syncthreads();            // orders mbarrier init + scalar/point/mask stores

    // ---- wait for the bulk copy (acquire orders TMA writes for generic reads)
    {
        unsigned mb = (unsigned)__cvta_generic_to_shared(&mbar);
        asm volatile(
            "{\n\t.reg .pred P;\n\t"
            "WAIT_%=:\n\t"
            "mbarrier.try_wait.parity.acquire.cta.shared::cta.b64 P, [%0], 0, 0x989680;\n\t"
            "@P bra DONE_%=;\n\t"
            "bra WAIT_%=;\n\t"
            "DONE_%=:\n\t}"
            :: "r"(mb) : "memory");
    }

    // ========== Phase A: geometry + pos-psums + neg-mask folded into data =====
    // Warp w owns rows [8w, 8w+8). Lane owns cols j0=lane, j1=lane+32.
    {
        const int j0 = lane, j1 = lane + 32;
        const float ax0 = ax[j0], ay0 = ay[j0], az0 = az[j0], an0 = an[j0];
        const float ax1 = ax[j1], ay1 = ay[j1], az1 = az[j1], an1 = an[j1];
        const bool  am0 = s_am[j0], am1 = s_am[j1];
        float cpsA = 0.0f, cpsB = 0.0f;
        int   ccA = 0, ccB = 0;
        #pragma unroll
        for (int r = 0; r < 8; ++r) {
            const int   i   = w * 8 + r;
            const float Xi = px[i], Yi = py_[i], Zi = pz[i], Ni = pn[i];
            const bool  pmk = s_pm[i];
            // mimic reference: (x2 - 2xy) + y2
            float d0 = (Ni - 2.0f * (Xi * ax0 + Yi * ay0 + Zi * az0)) + an0;
            float d1 = (Ni - 2.0f * (Xi * ax1 + Yi * ay1 + Zi * az1)) + an1;
            float m0 = sm[i * NMAT + j0];
            float m1 = sm[i * NMAT + j1];
            const bool c0 = (d0 < R2_POS) && pmk && am0;
            const bool c1 = (d1 < R2_POS) && pmk && am1;
            const float p0 = c0 ? -m0 : 0.0f;
            const float p1 = c1 ? -m1 : 0.0f;
            // row psum via fixed-point hardware reduction (abs error < 2e-5)
            int rps = __reduce_add_sync(0xFFFFFFFFu, __float2int_rn((p0 + p1) * FXS));
            int rc  = __reduce_add_sync(0xFFFFFFFFu, (int)c0 + (int)c1);
            if (lane == 0) {
                row_ps[i]  = (float)rps * (1.0f / FXS);
                row_cnt[i] = rc;
            }
            cpsA += p0; cpsB += p1; ccA += (int)c0; ccB += (int)c1;
            // fold neg mask into the data: non-neg interior -> -3e9 (fmax kills it)
            if (!(d0 > R2_NEG)) sm[i * NMAT + j0] = NEGBIG;
            if (!(d1 > R2_NEG)) sm[i * NMAT + j1] = NEGBIG;
        }
        colp[w][j0] = cpsA; colp[w][j1] = cpsB;
        colc[w][j0] = ccA;  colc[w][j1] = ccB;
    }
    __syncthreads();

    // ========== Phase B: branch-free loss sweeps (rows: pass 0, cols: pass 1) ==
    const int pass = tid >> 7;
    const int rr   = tid & 127;
    const int idx  = rr & 63;
    const int h    = rr >> 6;
    const int g    = (pass << 6) | idx;

    float psum; int cnt; float slack_m;
    if (pass == 0) {
        psum = row_ps[idx]; cnt = row_cnt[idx];
        slack_m = sm[idx * NMAT + KPTS];
    } else {
        float p = 0.0f; int c = 0;
        #pragma unroll
        for (int t = 0; t < 8; ++t) { p += colp[t][idx]; c += colc[t][idx]; }
        psum = p; cnt = c;
        slack_m = sm[KPTS * NMAT + idx];
    }
    const float base = (cnt ? __fdividef(psum, (float)cnt) : -slack_m) + GAMMA_C;

    float sA = 0.0f, sB = 0.0f;
    if (pass == 0) {
        const float* row = &sm[idx * NMAT + h * 32];
        #pragma unroll
        for (int jj = 0; jj < 16; ++jj) {
            sA += fmaxf(base + row[jj],      0.0f);
            sB += fmaxf(base + row[jj + 16], 0.0f);
        }
    } else {
        const float* colptr = &sm[(h * 32) * NMAT + idx];
        #pragma unroll
        for (int kk = 0; kk < 16; ++kk) {
            sA += fmaxf(base + colptr[kk * NMAT],        0.0f);
            sB += fmaxf(base + colptr[(kk + 16) * NMAT], 0.0f);
        }
    }
    comb_s[g][h] = sA + sB;
    __syncthreads();

    float acc = 0.0f;
    if (h == 0) {
        float st = comb_s[g][0] + comb_s[g][1];
        if (cnt) st += fmaxf(base + slack_m, 0.0f);   // slack entry: !row_none / !col_none
        acc = __logf(st + 1.0f);
    }

    // ---- block reduce ----
    #pragma unroll
    for (int o = 16; o; o >>= 1) acc += __shfl_xor_sync(0xFFFFFFFFu, acc, o);
    if (lane == 0) warp_sum[w] = acc;
    __syncthreads();
    if (tid == 0) {
        float tot = 0.0f;
        #pragma unroll
        for (int i = 0; i < 8; ++i) tot += warp_sum[i];
        g_partial[b] = tot;
        __threadfence();
        unsigned prev = atomicAdd(&g_done, 1u);
        s_last = (prev == BATCH - 1) ? 1 : 0;
    }
    __syncthreads();

    // ---- last block finalizes (no extra launch) ----
    if (s_last) {
        __threadfence();
        double d = 0.0;
        for (int i = tid; i < BATCH; i += 256) d += (double)g_partial[i];
        #pragma unroll
        for (int o = 16; o; o >>= 1) d += __shfl_xor_sync(0xFFFFFFFFu, d, o);
        if (lane == 0) dsum[w] = d;
        __syncthreads();
        if (tid == 0) {
            double t = 0.0;
            #pragma unroll
            for (int i = 0; i < 8; ++i) t += dsum[i];
            out[0] = (float)(t * (1.0 / (2.0 * (double)BATCH * (double)KPTS)));
            g_done = 0u;   // self-reset -> graph-replay deterministic
        }
    }
}

extern "C" void kernel_launch(void* const* d_in, const int* in_sizes, int n_in,
                              void* d_out, int out_size) {
    const float* pos_pts = (const float*)d_in[0];
    const float* anc_pts = (const float*)d_in[1];
    const void*  pos_m   = d_in[2];
    const void*  anc_m   = d_in[3];
    const float* ms      = (const float*)d_in[4];
    const float* T       = (const float*)d_in[5];

    loss_kernel<<<BATCH, 256>>>(pos_pts, anc_pts, pos_m, anc_m, ms, T, (float*)d_out);
}

// round 13
// speedup vs baseline: 1.8176x; 1.0472x over previous
#include <cuda_runtime.h>
#include <math.h>
#include <stdint.h>

#define BATCH 4096
#define KPTS  64
#define NMAT  65
#define TILE  (NMAT * NMAT)   /* 4225 */
#define GAMMA_C 0.5f
#define R2_POS  0.36f   /* 0.6^2  */
#define R2_NEG  1.44f   /* 1.2^2  */
#define NEGBIG  (-3.0e9f)
#define FXS     1048576.0f      /* 2^20 fixed-point scale for psum REDUX */
#define ABS2MASK 0x7FFFFFFF7FFFFFFFULL

__device__ float        g_partial[BATCH];   // per-block partial sums
__device__ unsigned int g_done;             // completion counter (self-resetting)

__device__ __forceinline__ bool read_mask(const void* p, size_t idx, unsigned mode) {
    if (mode & 2u) return ((const float*)p)[idx] != 0.0f;
    if (mode & 1u) return ((const uint8_t*)p)[idx] != 0;
    return ((const int*)p)[idx] != 0;
}

#define PACK2(d, lo, hi) \
    asm("mov.b64 %0, {%1, %2};" : "=l"(d) : "r"(lo), "r"(hi))
#define ADD2(d, a, b) \
    asm("add.rn.f32x2 %0, %1, %2;" : "=l"(d) : "l"(a), "l"(b))
#define UNPACK2(lo, hi, s) \
    asm("mov.b64 {%0, %1}, %2;" : "=r"(lo), "=r"(hi) : "l"(s))

// relu-sum step: acc2 += (x2 + |x2|)  where x2 = m2 + base2   (packed f32x2)
__device__ __forceinline__ void relu2_acc(unsigned long long& acc2,
                                          unsigned long long m2,
                                          unsigned long long base2) {
    unsigned long long x2, r2;
    ADD2(x2, m2, base2);
    unsigned long long a2 = x2 & ABS2MASK;   // packed abs (one LOP)
    ADD2(r2, x2, a2);                        // x + |x| = 2*relu(x), exact
    ADD2(acc2, acc2, r2);
}

__global__ __launch_bounds__(256, 7) void loss_kernel(
    const float* __restrict__ pos_pts,   // (B,K,3)
    const float* __restrict__ anc_pts,   // (B,K,3)
    const void*  __restrict__ pos_m,     // (B,K) bool-ish
    const void*  __restrict__ anc_m,     // (B,K)
    const float* __restrict__ ms,        // (B,N,N)
    const float* __restrict__ T,         // (4,4)
    float*       __restrict__ out)
{
    __shared__ __align__(16) float smraw[TILE + 4];  // stride 65 (odd): rows AND cols conflict-free
    __shared__ __align__(8) unsigned long long mbar; // TMA completion barrier
    __shared__ float px[KPTS], py_[KPTS], pz[KPTS], pn[KPTS];
    __shared__ float ax[KPTS], ay[KPTS], az[KPTS], an[KPTS];   // ax/ay/az pre-scaled by -2
    __shared__ unsigned char s_pm[KPTS], s_am[KPTS];
    __shared__ float row_ps[KPTS];
    __shared__ int   row_cnt[KPTS];
    __shared__ float colp[8][KPTS];      // per-warp column psum partials
    __shared__ int   colc[8][KPTS];
    __shared__ float comb_s[128][2];
    __shared__ float  warp_sum[8];
    __shared__ double dsum[8];
    __shared__ int    s_last;

    const int b    = blockIdx.x;
    const int tid  = threadIdx.x;
    const int lane = tid & 31;
    const int w    = tid >> 5;

    // ---- tile copy via ONE bulk-TMA request (16B aligned both sides).
    const float* msb  = ms + (size_t)b * TILE;
    const int    head = (4 - (b & 3)) & 3;
    float* sm = smraw + ((4 - head) & 3);
    const int nvec   = (TILE - head) >> 2;
    const int nbytes = nvec << 4;
    {
        unsigned mb   = (unsigned)__cvta_generic_to_shared(&mbar);
        unsigned sdst = (unsigned)__cvta_generic_to_shared(sm + head);
        if (tid == 0) {
            asm volatile("mbarrier.init.shared.b64 [%0], 1;" :: "r"(mb));
            asm volatile("mbarrier.arrive.expect_tx.shared.b64 _, [%0], %1;"
                         :: "r"(mb), "r"(nbytes));
            asm volatile("cp.async.bulk.shared::cta.global.mbarrier::complete_tx::bytes "
                         "[%0], [%1], %2, [%3];"
                         :: "r"(sdst), "l"(msb + head), "r"(nbytes), "r"(mb) : "memory");
        }
        if (tid < head) sm[tid] = msb[tid];                 // head scalars (<=3)
        const int tstart = head + (nvec << 2);
        const int tcnt   = TILE - tstart;                   // tail scalars (<=3)
        if (tid >= 4 && tid < 4 + tcnt) sm[tstart + (tid - 4)] = msb[tstart + (tid - 4)];
    }

    // ---- per-warp mask dtype detection (no block barrier) ----
    unsigned mode;
    {
        unsigned v = ((const unsigned int*)pos_m)[lane];
        unsigned f = (v == 0x3F800000u) ? 2u : ((v > 1u) ? 1u : 0u);
        mode = __reduce_or_sync(0xFFFFFFFFu, f);
    }

    // ---- points / transformed anchors (pre-scaled -2x) / masks ----
    if (tid < 64) {
        const float* p = pos_pts + ((size_t)b * KPTS + tid) * 3;
        float x = p[0], y = p[1], z = p[2];
        px[tid] = x; py_[tid] = y; pz[tid] = z;
        pn[tid] = x * x + y * y + z * z;
    } else if (tid < 128) {
        int k = tid - 64;
        const float* p = anc_pts + ((size_t)b * KPTS + k) * 3;
        float x = p[0], y = p[1], z = p[2];
        float X = T[0] * x + T[1] * y + T[2]  * z + T[3];
        float Y = T[4] * x + T[5] * y + T[6]  * z + T[7];
        float Z = T[8] * x + T[9] * y + T[10] * z + T[11];
        ax[k] = -2.0f * X; ay[k] = -2.0f * Y; az[k] = -2.0f * Z;
        an[k] = X * X + Y * Y + Z * Z;
    } else if (tid < 192) {
        int k = tid - 128;
        s_pm[k] = read_mask(pos_m, (size_t)b * KPTS + k, mode) ? 1 : 0;
    } else {
        int k = tid - 192;
        s_am[k] = read_mask(anc_m, (size_t)b * KPTS + k, mode) ? 1 : 0;
    }
    __syncthreads();            // orders mbarrier init + scalar/point/mask stores

    // ---- wait for the bulk copy ----
    {
        unsigned mb = (unsigned)__cvta_generic_to_shared(&mbar);
        asm volatile(
            "{\n\t.reg .pred P;\n\t"
            "WAIT_%=:\n\t"
            "mbarrier.try_wait.parity.acquire.cta.shared::cta.b64 P, [%0], 0, 0x989680;\n\t"
            "@P bra DONE_%=;\n\t"
            "bra WAIT_%=;\n\t"
            "DONE_%=:\n\t}"
            :: "r"(mb) : "memory");
    }

    // ========== Phase A: geometry + pos-psums + neg-mask folded into data =====
    {
        const int j0 = lane, j1 = lane + 32;
        const float ax0 = ax[j0], ay0 = ay[j0], az0 = az[j0], an0 = an[j0];
        const float ax1 = ax[j1], ay1 = ay[j1], az1 = az[j1], an1 = an[j1];
        const bool  am0 = s_am[j0], am1 = s_am[j1];
        float cpsA = 0.0f, cpsB = 0.0f;
        int   ccA = 0, ccB = 0;
        #pragma unroll
        for (int r = 0; r < 8; ++r) {
            const int   i   = w * 8 + r;
            const float Xi = px[i], Yi = py_[i], Zi = pz[i], Ni = pn[i];
            const bool  pmk = s_pm[i];
            // d = (pn + an) + x·(-2a)  — FADD + 3 FMA per distance
            float d0 = fmaf(Xi, ax0, fmaf(Yi, ay0, fmaf(Zi, az0, Ni + an0)));
            float d1 = fmaf(Xi, ax1, fmaf(Yi, ay1, fmaf(Zi, az1, Ni + an1)));
            float m0 = sm[i * NMAT + j0];
            float m1 = sm[i * NMAT + j1];
            const bool c0 = (d0 < R2_POS) && pmk && am0;
            const bool c1 = (d1 < R2_POS) && pmk && am1;
            const float p0 = c0 ? -m0 : 0.0f;
            const float p1 = c1 ? -m1 : 0.0f;
            // row psum via fixed-point hardware reduction (abs error < 2e-5)
            int rps = __reduce_add_sync(0xFFFFFFFFu, __float2int_rn((p0 + p1) * FXS));
            int rc  = __reduce_add_sync(0xFFFFFFFFu, (int)c0 + (int)c1);
            if (lane == 0) {
                row_ps[i]  = (float)rps * (1.0f / FXS);
                row_cnt[i] = rc;
            }
            cpsA += p0; cpsB += p1; ccA += (int)c0; ccB += (int)c1;
            // fold neg mask into the data: non-neg interior -> -3e9 (fmax kills it)
            if (!(d0 > R2_NEG)) sm[i * NMAT + j0] = NEGBIG;
            if (!(d1 > R2_NEG)) sm[i * NMAT + j1] = NEGBIG;
        }
        colp[w][j0] = cpsA; colp[w][j1] = cpsB;
        colc[w][j0] = ccA;  colc[w][j1] = ccB;
    }
    __syncthreads();

    // ========== Phase B: packed-f32x2 loss sweeps (rows: pass 0, cols: pass 1) ==
    const int pass = tid >> 7;
    const int rr   = tid & 127;
    const int idx  = rr & 63;
    const int h    = rr >> 6;
    const int g    = (pass << 6) | idx;

    float psum; int cnt; float slack_m;
    if (pass == 0) {
        psum = row_ps[idx]; cnt = row_cnt[idx];
        slack_m = sm[idx * NMAT + KPTS];
    } else {
        float p = 0.0f; int c = 0;
        #pragma unroll
        for (int t = 0; t < 8; ++t) { p += colp[t][idx]; c += colc[t][idx]; }
        psum = p; cnt = c;
        slack_m = sm[KPTS * NMAT + idx];
    }
    const float base = (cnt ? __fdividef(psum, (float)cnt) : -slack_m) + GAMMA_C;

    unsigned long long base2, acc2 = 0ULL;
    {
        const unsigned bu = __float_as_uint(base);
        PACK2(base2, bu, bu);
    }
    if (pass == 0) {
        const unsigned* row = (const unsigned*)&sm[idx * NMAT + h * 32];
        #pragma unroll
        for (int jj = 0; jj < 16; ++jj) {
            unsigned long long m2;
            PACK2(m2, row[jj], row[jj + 16]);
            relu2_acc(acc2, m2, base2);
        }
    } else {
        const unsigned* colptr = (const unsigned*)&sm[(h * 32) * NMAT + idx];
        #pragma unroll
        for (int kk = 0; kk < 16; ++kk) {
            unsigned long long m2;
            PACK2(m2, colptr[kk * NMAT], colptr[(kk + 16) * NMAT]);
            relu2_acc(acc2, m2, base2);
        }
    }
    {
        unsigned lo, hi;
        UNPACK2(lo, hi, acc2);
        comb_s[g][h] = 0.5f * (__uint_as_float(lo) + __uint_as_float(hi));
    }
    __syncthreads();

    float acc = 0.0f;
    if (h == 0) {
        float st = comb_s[g][0] + comb_s[g][1];
        if (cnt) st += fmaxf(base + slack_m, 0.0f);   // slack entry: !row_none / !col_none
        acc = __logf(st + 1.0f);
    }

    // ---- block reduce ----
    #pragma unroll
    for (int o = 16; o; o >>= 1) acc += __shfl_xor_sync(0xFFFFFFFFu, acc, o);
    if (lane == 0) warp_sum[w] = acc;
    __syncthreads();
    if (tid == 0) {
        float tot = 0.0f;
        #pragma unroll
        for (int i = 0; i < 8; ++i) tot += warp_sum[i];
        g_partial[b] = tot;
        __threadfence();
        unsigned prev = atomicAdd(&g_done, 1u);
        s_last = (prev == BATCH - 1) ? 1 : 0;
    }
    __syncthreads();

    // ---- last block finalizes (no extra launch) ----
    if (s_last) {
        __threadfence();
        double d = 0.0;
        for (int i = tid; i < BATCH; i += 256) d += (double)g_partial[i];
        #pragma unroll
        for (int o = 16; o; o >>= 1) d += __shfl_xor_sync(0xFFFFFFFFu, d, o);
        if (lane == 0) dsum[w] = d;
        __syncthreads();
        if (tid == 0) {
            double t = 0.0;
            #pragma unroll
            for (int i = 0; i < 8; ++i) t += dsum[i];
            out[0] = (float)(t * (1.0 / (2.0 * (double)BATCH * (double)KPTS)));
            g_done = 0u;   // self-reset -> graph-replay deterministic
        }
    }
}

extern "C" void kernel_launch(void* const* d_in, const int* in_sizes, int n_in,
                              void* d_out, int out_size) {
    const float* pos_pts = (const float*)d_in[0];
    const float* anc_pts = (const float*)d_in[1];
    const void*  pos_m   = d_in[2];
    const void*  anc_m   = d_in[3];
    const float* ms      = (const float*)d_in[4];
    const float* T       = (const float*)d_in[5];

    loss_kernel<<<BATCH, 256>>>(pos_pts, anc_pts, pos_m, anc_m, ms, T, (float*)d_out);
}